// round 3
// baseline (speedup 1.0000x reference)
#include <cuda_runtime.h>
#include <math.h>

#define NN 3000
#define E1 256
#define E2 128
#define NZ 64

__device__ float g_t1[NN * E1];
__device__ float g_z1[NN * E1];
__device__ float g_t2[NN * E2];
__device__ float g_z2[NN * E2];
__device__ float g_t3[NN * NZ];
__device__ float g_z3[NN * NZ];

// ---------------------------------------------------------------------------
// SGEMM 128x128 blocktile, BK=8, 256 threads, 8x8 microtile,
// register-staged double-buffered smem.
// C[M,N] = act(A[M,K] @ B[K,N]).  Requires N % 128 == 0, K % 8 == 0.
// M row-guarded. ACT: 0 = identity, 1 = tanh.
// ---------------------------------------------------------------------------
template <int ACT>
__global__ __launch_bounds__(256) void sgemm128(const float* __restrict__ A,
                                                const float* __restrict__ B,
                                                float* __restrict__ C,
                                                int M, int N, int K) {
    __shared__ float As[2][8][128];   // transposed: As[buf][k][row]
    __shared__ float Bs[2][8][128];

    const int tid  = threadIdx.x;
    const int row0 = blockIdx.y * 128;
    const int col0 = blockIdx.x * 128;

    const int tx = tid & 15;        // col group (8 cols)
    const int ty = tid >> 4;        // row group (8 rows)

    // A load: 128 rows x 8 cols = 256 float4
    const int a_row = tid >> 1;
    const int a_col = (tid & 1) << 2;
    // B load: 8 rows x 128 cols = 256 float4
    const int b_row = tid >> 5;
    const int b_col = (tid & 31) << 2;

    float acc[8][8];
#pragma unroll
    for (int i = 0; i < 8; i++)
#pragma unroll
        for (int j = 0; j < 8; j++) acc[i][j] = 0.0f;

    const int gr = row0 + a_row;
    const bool a_ok = (gr < M);
    const float* a_ptr = A + (size_t)gr * K + a_col;
    const float* b_ptr = B + (size_t)b_row * N + col0 + b_col;

    // Preload tile 0 into buffer 0
    float4 av = make_float4(0.f, 0.f, 0.f, 0.f);
    if (a_ok) av = *reinterpret_cast<const float4*>(a_ptr);
    As[0][a_col + 0][a_row] = av.x;
    As[0][a_col + 1][a_row] = av.y;
    As[0][a_col + 2][a_row] = av.z;
    As[0][a_col + 3][a_row] = av.w;
    *reinterpret_cast<float4*>(&Bs[0][b_row][b_col]) =
        *reinterpret_cast<const float4*>(b_ptr);
    __syncthreads();

    int cur = 0;
    for (int k0 = 0; k0 < K; k0 += 8) {
        const bool has_next = (k0 + 8) < K;
        float4 an = make_float4(0.f, 0.f, 0.f, 0.f);
        float4 bn = make_float4(0.f, 0.f, 0.f, 0.f);
        if (has_next) {
            if (a_ok) an = *reinterpret_cast<const float4*>(a_ptr + k0 + 8);
            bn = *reinterpret_cast<const float4*>(b_ptr + (size_t)(k0 + 8) * N);
        }

#pragma unroll
        for (int k = 0; k < 8; k++) {
            float a[8], b[8];
            *reinterpret_cast<float4*>(&a[0]) =
                *reinterpret_cast<const float4*>(&As[cur][k][ty * 8]);
            *reinterpret_cast<float4*>(&a[4]) =
                *reinterpret_cast<const float4*>(&As[cur][k][ty * 8 + 4]);
            *reinterpret_cast<float4*>(&b[0]) =
                *reinterpret_cast<const float4*>(&Bs[cur][k][tx * 8]);
            *reinterpret_cast<float4*>(&b[4]) =
                *reinterpret_cast<const float4*>(&Bs[cur][k][tx * 8 + 4]);
#pragma unroll
            for (int i = 0; i < 8; i++)
#pragma unroll
                for (int j = 0; j < 8; j++)
                    acc[i][j] = fmaf(a[i], b[j], acc[i][j]);
        }

        if (has_next) {
            const int nxt = cur ^ 1;
            As[nxt][a_col + 0][a_row] = an.x;
            As[nxt][a_col + 1][a_row] = an.y;
            As[nxt][a_col + 2][a_row] = an.z;
            As[nxt][a_col + 3][a_row] = an.w;
            *reinterpret_cast<float4*>(&Bs[nxt][b_row][b_col]) = bn;
            __syncthreads();
            cur = nxt;
        }
    }

#pragma unroll
    for (int i = 0; i < 8; i++) {
        int r = row0 + ty * 8 + i;
        if (r >= M) continue;
        float v[8];
#pragma unroll
        for (int j = 0; j < 8; j++)
            v[j] = (ACT == 1) ? tanhf(acc[i][j]) : acc[i][j];
        float* crow = C + (size_t)r * N + col0 + tx * 8;
        *reinterpret_cast<float4*>(crow)     = make_float4(v[0], v[1], v[2], v[3]);
        *reinterpret_cast<float4*>(crow + 4) = make_float4(v[4], v[5], v[6], v[7]);
    }
}

// ---------------------------------------------------------------------------
// SGEMM 128x64 blocktile, BK=8, 256 threads, 8x4 microtile (for N=64).
// ---------------------------------------------------------------------------
template <int ACT>
__global__ __launch_bounds__(256) void sgemm64(const float* __restrict__ A,
                                               const float* __restrict__ B,
                                               float* __restrict__ C,
                                               int M, int N, int K) {
    __shared__ float As[8][128];
    __shared__ float Bs[8][64];

    const int tid  = threadIdx.x;
    const int row0 = blockIdx.y * 128;
    const int col0 = blockIdx.x * 64;

    const int tx = tid & 15;
    const int ty = tid >> 4;

    const int a_row = tid >> 1;
    const int a_col = (tid & 1) << 2;
    const int b_row = tid >> 4;
    const int b_col = (tid & 15) << 2;

    float acc[8][4];
#pragma unroll
    for (int i = 0; i < 8; i++)
#pragma unroll
        for (int j = 0; j < 4; j++) acc[i][j] = 0.0f;

    const int gr = row0 + a_row;
    const bool a_ok = (gr < M);
    const float* a_ptr = A + (size_t)gr * K + a_col;

    for (int k0 = 0; k0 < K; k0 += 8) {
        float4 av = make_float4(0.f, 0.f, 0.f, 0.f);
        if (a_ok) av = *reinterpret_cast<const float4*>(a_ptr + k0);
        As[a_col + 0][a_row] = av.x;
        As[a_col + 1][a_row] = av.y;
        As[a_col + 2][a_row] = av.z;
        As[a_col + 3][a_row] = av.w;
        if (tid < 128) {
            float4 bv = *reinterpret_cast<const float4*>(
                B + (size_t)(k0 + b_row) * N + col0 + b_col);
            *reinterpret_cast<float4*>(&Bs[b_row][b_col]) = bv;
        }
        __syncthreads();

#pragma unroll
        for (int k = 0; k < 8; k++) {
            float a[8], b[4];
            *reinterpret_cast<float4*>(&a[0]) =
                *reinterpret_cast<const float4*>(&As[k][ty * 8]);
            *reinterpret_cast<float4*>(&a[4]) =
                *reinterpret_cast<const float4*>(&As[k][ty * 8 + 4]);
            *reinterpret_cast<float4*>(&b[0]) =
                *reinterpret_cast<const float4*>(&Bs[k][tx * 4]);
#pragma unroll
            for (int i = 0; i < 8; i++)
#pragma unroll
                for (int j = 0; j < 4; j++)
                    acc[i][j] = fmaf(a[i], b[j], acc[i][j]);
        }
        __syncthreads();
    }

#pragma unroll
    for (int i = 0; i < 8; i++) {
        int r = row0 + ty * 8 + i;
        if (r >= M) continue;
        float4 v;
        if (ACT == 1) {
            v = make_float4(tanhf(acc[i][0]), tanhf(acc[i][1]),
                            tanhf(acc[i][2]), tanhf(acc[i][3]));
        } else {
            v = make_float4(acc[i][0], acc[i][1], acc[i][2], acc[i][3]);
        }
        *reinterpret_cast<float4*>(C + (size_t)r * N + col0 + tx * 4) = v;
    }
}

// ---------------------------------------------------------------------------
// out[i,j] = sigmoid(dot(Z[i,:], Z[j,:])), Z: [M, 64], out: [M, M]
// ---------------------------------------------------------------------------
__global__ __launch_bounds__(256) void zzT_sigmoid(const float* __restrict__ Z,
                                                   float* __restrict__ out,
                                                   int M) {
    __shared__ float As[64][65];
    __shared__ float Bs[64][65];

    const int tid  = threadIdx.x;
    const int row0 = blockIdx.y << 6;
    const int col0 = blockIdx.x << 6;

    for (int t = tid; t < 64 * 16; t += 256) {
        int r = t >> 4;
        int c = (t & 15) << 2;
        float4 va = make_float4(0.f, 0.f, 0.f, 0.f);
        int gra = row0 + r;
        if (gra < M) va = *reinterpret_cast<const float4*>(Z + (size_t)gra * 64 + c);
        As[r][c] = va.x; As[r][c + 1] = va.y; As[r][c + 2] = va.z; As[r][c + 3] = va.w;
        float4 vb = make_float4(0.f, 0.f, 0.f, 0.f);
        int grb = col0 + r;
        if (grb < M) vb = *reinterpret_cast<const float4*>(Z + (size_t)grb * 64 + c);
        Bs[r][c] = vb.x; Bs[r][c + 1] = vb.y; Bs[r][c + 2] = vb.z; Bs[r][c + 3] = vb.w;
    }
    __syncthreads();

    const int tx = tid & 15;
    const int ty = tid >> 4;
    float acc[4][4];
#pragma unroll
    for (int i = 0; i < 4; i++)
#pragma unroll
        for (int j = 0; j < 4; j++) acc[i][j] = 0.0f;

#pragma unroll 8
    for (int k = 0; k < 64; k++) {
        float a[4], b[4];
#pragma unroll
        for (int i = 0; i < 4; i++) a[i] = As[ty * 4 + i][k];
#pragma unroll
        for (int j = 0; j < 4; j++) b[j] = Bs[tx * 4 + j][k];
#pragma unroll
        for (int i = 0; i < 4; i++)
#pragma unroll
            for (int j = 0; j < 4; j++)
                acc[i][j] = fmaf(a[i], b[j], acc[i][j]);
    }

#pragma unroll
    for (int i = 0; i < 4; i++) {
        int r = row0 + ty * 4 + i;
        if (r >= M) continue;
#pragma unroll
        for (int j = 0; j < 4; j++) {
            int c = col0 + tx * 4 + j;
            if (c < M)
                out[(size_t)r * M + c] = 1.0f / (1.0f + expf(-acc[i][j]));
        }
    }
}

// ---------------------------------------------------------------------------
extern "C" void kernel_launch(void* const* d_in, const int* in_sizes, int n_in,
                              void* d_out, int out_size) {
    (void)in_sizes; (void)n_in; (void)out_size;

    const float* omics1 = (const float*)d_in[0];
    const float* omics2 = (const float*)d_in[1];
    const float* adjs[4] = {(const float*)d_in[2], (const float*)d_in[3],
                            (const float*)d_in[4], (const float*)d_in[5]};
    const float* xs[4] = {omics1, omics2, omics1, omics2};

    float* out = (float*)d_out;

    float *t1, *z1, *t2, *z2, *t3, *z3;
    cudaGetSymbolAddress((void**)&t1, g_t1);
    cudaGetSymbolAddress((void**)&z1, g_z1);
    cudaGetSymbolAddress((void**)&t2, g_t2);
    cudaGetSymbolAddress((void**)&z2, g_z2);
    cudaGetSymbolAddress((void**)&t3, g_t3);
    cudaGetSymbolAddress((void**)&z3, g_z3);

    const int mblocks = (NN + 127) / 128;           // 24
    const dim3 g256(E1 / 128, mblocks);             // 2 x 24
    const dim3 g128(E2 / 128, mblocks);             // 1 x 24
    const dim3 g64(1, mblocks);
    const int nt = (NN + 63) / 64;                  // 47
    const dim3 gzz(nt, nt);

    for (int e = 0; e < 4; e++) {
        const float* X   = xs[e];
        const float* adj = adjs[e];
        const float* w1  = (const float*)d_in[6 + e * 3 + 0];
        const float* w2  = (const float*)d_in[6 + e * 3 + 1];
        const float* w3  = (const float*)d_in[6 + e * 3 + 2];
        float* out_e = out + (size_t)e * NN * NN;

        sgemm128<1><<<g256, 256>>>(X,   w1, t1, NN, E1, NN);   // T1 = tanh(X @ W1)
        sgemm128<0><<<g256, 256>>>(adj, t1, z1, NN, E1, NN);   // Z1 = adj @ T1
        sgemm128<1><<<g128, 256>>>(z1,  w2, t2, NN, E2, E1);   // T2 = tanh(Z1 @ W2)
        sgemm128<0><<<g128, 256>>>(adj, t2, z2, NN, E2, NN);   // Z2 = adj @ T2
        sgemm64<0><<<g64,  256>>>(z2,  w3, t3, NN, NZ, E2);    // T3 = Z2 @ W3
        sgemm64<0><<<g64,  256>>>(adj, t3, z3, NN, NZ, NN);    // Z3 = adj @ T3
        zzT_sigmoid<<<gzz, 256>>>(z3, out_e, NN);              // sigmoid(Z3 @ Z3^T)
    }
}

// round 4
// speedup vs baseline: 3.4829x; 3.4829x over previous
#include <cuda_runtime.h>
#include <math.h>

#define NN 3000
#define E1 256
#define E2 128
#define NZ 64

// Per-encoder scratch (batched: 4 encoders side by side)
__device__ float g_t1[4 * NN * E1];
__device__ float g_z1[4 * NN * E1];
__device__ float g_t2[4 * NN * E2];
__device__ float g_z2[4 * NN * E2];
__device__ float g_t3[4 * NN * NZ];
__device__ float g_z3[4 * NN * NZ];
// Split-K partials: max(4*2*NN*E2, 4*4*NN*NZ) = 3,072,000 floats
__device__ float g_part[4 * 2 * NN * E2];

struct Batch4 {
    const float* A[4];
    const float* B[4];
    float* C[4];
};

// ---------------------------------------------------------------------------
// Batched SGEMM: C_e[M,N] = act(A_e[M,K] @ B_e[K,N]) for e in [0,4)
// BM=128, BN template (128 or 64), BK=8, 256 threads.
// Microtile 8 x (BN/16). Double-buffered smem, register-staged prefetch.
// blockIdx.z = e*SPLITK + s; split s covers K range [s*kChunk, min(K,(s+1)*kChunk)).
// kChunk must be a multiple of 8. SPLITK>1 writes raw partials to `part`
// at offset (e*SPLITK+s)*M*N (deterministic; no atomics).
// ---------------------------------------------------------------------------
template <int BN, int ACT, int SPLITK>
__global__ __launch_bounds__(256, 2) void gemm_batched(
    Batch4 p, int M, int N, int K, int kChunk, float* part) {
    constexpr int TN = BN / 16;
    __shared__ float As[2][8][128];
    __shared__ float Bs[2][8][BN];

    const int e = blockIdx.z / SPLITK;
    const int s = blockIdx.z % SPLITK;
    const float* __restrict__ A = p.A[e];
    const float* __restrict__ B = p.B[e];

    const int k_begin = s * kChunk;
    const int k_end = min(K, k_begin + kChunk);

    const int tid  = threadIdx.x;
    const int row0 = blockIdx.y * 128;
    const int col0 = blockIdx.x * BN;

    const int tx = tid & 15;        // col group (TN cols)
    const int ty = tid >> 4;        // row group (8 rows)

    // A tile load: 128 rows x 8 k = 256 float4 (1 per thread)
    const int a_row = tid >> 1;
    const int a_col = (tid & 1) << 2;
    // B tile load: 8 k x BN = 2*BN float4
    constexpr int BNL = BN / 4;
    const int b_row = tid / BNL;
    const int b_col = (tid % BNL) * 4;
    const bool b_act = (tid < 2 * BN);

    float acc[8][TN];
#pragma unroll
    for (int i = 0; i < 8; i++)
#pragma unroll
        for (int j = 0; j < TN; j++) acc[i][j] = 0.0f;

    const int gr = row0 + a_row;
    const bool a_ok = (gr < M);
    const float* a_ptr = A + (size_t)gr * K + a_col;
    const float* b_ptr = B + (size_t)b_row * N + col0 + b_col;

    // Preload first tile
    {
        float4 av = make_float4(0.f, 0.f, 0.f, 0.f);
        if (a_ok) av = *reinterpret_cast<const float4*>(a_ptr + k_begin);
        As[0][a_col + 0][a_row] = av.x;
        As[0][a_col + 1][a_row] = av.y;
        As[0][a_col + 2][a_row] = av.z;
        As[0][a_col + 3][a_row] = av.w;
        if (b_act)
            *reinterpret_cast<float4*>(&Bs[0][b_row][b_col]) =
                *reinterpret_cast<const float4*>(b_ptr + (size_t)k_begin * N);
    }
    __syncthreads();

    int cur = 0;
    for (int k0 = k_begin; k0 < k_end; k0 += 8) {
        const bool has_next = (k0 + 8) < k_end;
        float4 an = make_float4(0.f, 0.f, 0.f, 0.f);
        float4 bn = make_float4(0.f, 0.f, 0.f, 0.f);
        if (has_next) {
            if (a_ok) an = *reinterpret_cast<const float4*>(a_ptr + k0 + 8);
            if (b_act) bn = *reinterpret_cast<const float4*>(b_ptr + (size_t)(k0 + 8) * N);
        }

#pragma unroll
        for (int k = 0; k < 8; k++) {
            float a[8], b[TN];
            *reinterpret_cast<float4*>(&a[0]) =
                *reinterpret_cast<const float4*>(&As[cur][k][ty * 8]);
            *reinterpret_cast<float4*>(&a[4]) =
                *reinterpret_cast<const float4*>(&As[cur][k][ty * 8 + 4]);
#pragma unroll
            for (int j0 = 0; j0 < TN; j0 += 4)
                *reinterpret_cast<float4*>(&b[j0]) =
                    *reinterpret_cast<const float4*>(&Bs[cur][k][tx * TN + j0]);
#pragma unroll
            for (int i = 0; i < 8; i++)
#pragma unroll
                for (int j = 0; j < TN; j++)
                    acc[i][j] = fmaf(a[i], b[j], acc[i][j]);
        }

        if (has_next) {
            const int nxt = cur ^ 1;
            As[nxt][a_col + 0][a_row] = an.x;
            As[nxt][a_col + 1][a_row] = an.y;
            As[nxt][a_col + 2][a_row] = an.z;
            As[nxt][a_col + 3][a_row] = an.w;
            if (b_act) *reinterpret_cast<float4*>(&Bs[nxt][b_row][b_col]) = bn;
            __syncthreads();
            cur = nxt;
        }
    }

    float* dst;
    if (SPLITK > 1)
        dst = part + (size_t)(e * SPLITK + s) * M * N;
    else
        dst = p.C[e];

#pragma unroll
    for (int i = 0; i < 8; i++) {
        int r = row0 + ty * 8 + i;
        if (r >= M) continue;
        float v[TN];
#pragma unroll
        for (int j = 0; j < TN; j++)
            v[j] = (ACT == 1 && SPLITK == 1) ? tanhf(acc[i][j]) : acc[i][j];
        float* crow = dst + (size_t)r * N + col0 + tx * TN;
#pragma unroll
        for (int j0 = 0; j0 < TN; j0 += 4)
            *reinterpret_cast<float4*>(crow + j0) =
                make_float4(v[j0], v[j0 + 1], v[j0 + 2], v[j0 + 3]);
    }
}

// ---------------------------------------------------------------------------
// Deterministic split-K reduce: out[e][i] = sum_s part[(e*S+s)*MN + i]
// ---------------------------------------------------------------------------
template <int S>
__global__ __launch_bounds__(256) void reduce_split(const float* __restrict__ part,
                                                    float* __restrict__ out, int MN) {
    const int e = blockIdx.z;
    const int i = (blockIdx.x * 256 + threadIdx.x) * 4;
    if (i >= MN) return;
    const float* pp = part + (size_t)e * S * MN + i;
    float4 acc = *reinterpret_cast<const float4*>(pp);
#pragma unroll
    for (int s = 1; s < S; s++) {
        float4 v = *reinterpret_cast<const float4*>(pp + (size_t)s * MN);
        acc.x += v.x; acc.y += v.y; acc.z += v.z; acc.w += v.w;
    }
    *reinterpret_cast<float4*>(out + (size_t)e * MN + i) = acc;
}

// ---------------------------------------------------------------------------
// Batched: out[e][i,j] = sigmoid(dot(Z_e[i,:], Z_e[j,:])), Z: [M,64]
// ---------------------------------------------------------------------------
__global__ __launch_bounds__(256) void zzT_sigmoid(const float* __restrict__ Zall,
                                                   float* __restrict__ outAll,
                                                   int M) {
    __shared__ float As[64][65];
    __shared__ float Bs[64][65];

    const int e = blockIdx.z;
    const float* Z = Zall + (size_t)e * M * 64;
    float* out = outAll + (size_t)e * M * M;

    const int tid  = threadIdx.x;
    const int row0 = blockIdx.y << 6;
    const int col0 = blockIdx.x << 6;

    for (int t = tid; t < 64 * 16; t += 256) {
        int r = t >> 4;
        int c = (t & 15) << 2;
        float4 va = make_float4(0.f, 0.f, 0.f, 0.f);
        int gra = row0 + r;
        if (gra < M) va = *reinterpret_cast<const float4*>(Z + (size_t)gra * 64 + c);
        As[r][c] = va.x; As[r][c + 1] = va.y; As[r][c + 2] = va.z; As[r][c + 3] = va.w;
        float4 vb = make_float4(0.f, 0.f, 0.f, 0.f);
        int grb = col0 + r;
        if (grb < M) vb = *reinterpret_cast<const float4*>(Z + (size_t)grb * 64 + c);
        Bs[r][c] = vb.x; Bs[r][c + 1] = vb.y; Bs[r][c + 2] = vb.z; Bs[r][c + 3] = vb.w;
    }
    __syncthreads();

    const int tx = tid & 15;
    const int ty = tid >> 4;
    float acc[4][4];
#pragma unroll
    for (int i = 0; i < 4; i++)
#pragma unroll
        for (int j = 0; j < 4; j++) acc[i][j] = 0.0f;

#pragma unroll 8
    for (int k = 0; k < 64; k++) {
        float a[4], b[4];
#pragma unroll
        for (int i = 0; i < 4; i++) a[i] = As[ty * 4 + i][k];
#pragma unroll
        for (int j = 0; j < 4; j++) b[j] = Bs[tx * 4 + j][k];
#pragma unroll
        for (int i = 0; i < 4; i++)
#pragma unroll
            for (int j = 0; j < 4; j++)
                acc[i][j] = fmaf(a[i], b[j], acc[i][j]);
    }

#pragma unroll
    for (int i = 0; i < 4; i++) {
        int r = row0 + ty * 4 + i;
        if (r >= M) continue;
#pragma unroll
        for (int j = 0; j < 4; j++) {
            int c = col0 + tx * 4 + j;
            if (c < M)
                out[(size_t)r * M + c] = 1.0f / (1.0f + expf(-acc[i][j]));
        }
    }
}

// ---------------------------------------------------------------------------
extern "C" void kernel_launch(void* const* d_in, const int* in_sizes, int n_in,
                              void* d_out, int out_size) {
    (void)in_sizes; (void)n_in; (void)out_size;

    const float* omics1 = (const float*)d_in[0];
    const float* omics2 = (const float*)d_in[1];
    const float* adjs[4] = {(const float*)d_in[2], (const float*)d_in[3],
                            (const float*)d_in[4], (const float*)d_in[5]};
    const float* xs[4] = {omics1, omics2, omics1, omics2};
    float* out = (float*)d_out;

    float *t1, *z1, *t2, *z2, *t3, *z3, *part;
    cudaGetSymbolAddress((void**)&t1, g_t1);
    cudaGetSymbolAddress((void**)&z1, g_z1);
    cudaGetSymbolAddress((void**)&t2, g_t2);
    cudaGetSymbolAddress((void**)&z2, g_z2);
    cudaGetSymbolAddress((void**)&t3, g_t3);
    cudaGetSymbolAddress((void**)&z3, g_z3);
    cudaGetSymbolAddress((void**)&part, g_part);

    const int mblocks = (NN + 127) / 128;  // 24

    Batch4 b1a, b1b, b2a, b2b, b3a, b3b;
    for (int e = 0; e < 4; e++) {
        const float* w1 = (const float*)d_in[6 + e * 3 + 0];
        const float* w2 = (const float*)d_in[6 + e * 3 + 1];
        const float* w3 = (const float*)d_in[6 + e * 3 + 2];
        float* t1e = t1 + (size_t)e * NN * E1;
        float* z1e = z1 + (size_t)e * NN * E1;
        float* t2e = t2 + (size_t)e * NN * E2;
        float* z2e = z2 + (size_t)e * NN * E2;
        float* t3e = t3 + (size_t)e * NN * NZ;

        b1a.A[e] = xs[e];   b1a.B[e] = w1;  b1a.C[e] = t1e;
        b1b.A[e] = adjs[e]; b1b.B[e] = t1e; b1b.C[e] = z1e;
        b2a.A[e] = z1e;     b2a.B[e] = w2;  b2a.C[e] = t2e;
        b2b.A[e] = adjs[e]; b2b.B[e] = t2e; b2b.C[e] = nullptr;  // split-K
        b3a.A[e] = z2e;     b3a.B[e] = w3;  b3a.C[e] = t3e;
        b3b.A[e] = adjs[e]; b3b.B[e] = t3e; b3b.C[e] = nullptr;  // split-K
    }

    // L1: T1 = tanh(X @ W1); Z1 = adj @ T1    [N=256, K=3000]
    gemm_batched<128, 1, 1><<<dim3(2, mblocks, 4), 256>>>(b1a, NN, E1, NN, NN, nullptr);
    gemm_batched<128, 0, 1><<<dim3(2, mblocks, 4), 256>>>(b1b, NN, E1, NN, NN, nullptr);
    // L2: T2 = tanh(Z1 @ W2) [N=128, K=256]; Z2 = adj @ T2 [split-K 2]
    gemm_batched<128, 1, 1><<<dim3(1, mblocks, 4), 256>>>(b2a, NN, E2, E1, E1, nullptr);
    gemm_batched<128, 0, 2><<<dim3(1, mblocks, 8), 256>>>(b2b, NN, E2, NN, 1504, part);
    reduce_split<2><<<dim3(NN * E2 / 1024, 1, 4), 256>>>(part, z2, NN * E2);
    // L3: T3 = Z2 @ W3 [N=64, K=128]; Z3 = adj @ T3 [split-K 4]
    gemm_batched<64, 0, 1><<<dim3(1, mblocks, 4), 256>>>(b3a, NN, NZ, E2, E2, nullptr);
    gemm_batched<64, 0, 4><<<dim3(1, mblocks, 16), 256>>>(b3b, NN, NZ, NN, 752, part);
    reduce_split<4><<<dim3((NN * NZ + 1023) / 1024, 1, 4), 256>>>(part, z3, NN * NZ);
    // Output: sigmoid(Z3 @ Z3^T) for all 4 encoders
    const int nt = (NN + 63) / 64;  // 47
    zzT_sigmoid<<<dim3(nt, nt, 4), 256>>>(z3, out, NN);
}

// round 7
// speedup vs baseline: 6.3090x; 1.8114x over previous
#include <cuda_runtime.h>
#include <cuda_bf16.h>
#include <math.h>
#include <stdint.h>

#define NN 3000
#define E1 256
#define E2 128
#define NZ 64
#define OM (NN * NN)

// ---------------- bf16 hi/lo scratch ----------------------------------------
__device__ unsigned short g_xh[2 * OM],        g_xl[2 * OM];         // omics [N,K]
__device__ unsigned short g_ajh[4 * OM],       g_ajl[4 * OM];        // adj   [N,K]
__device__ unsigned short g_w1h[4 * NN * E1],  g_w1l[4 * NN * E1];   // W1^T [E1,NN]
__device__ unsigned short g_w2h[4 * E1 * E2],  g_w2l[4 * E1 * E2];   // W2^T [E2,E1]
__device__ unsigned short g_w3h[4 * E2 * NZ],  g_w3l[4 * E2 * NZ];   // W3^T [NZ,E2]
__device__ unsigned short g_t1h[4 * NN * E1],  g_t1l[4 * NN * E1];   // T1^T [E1,NN]
__device__ unsigned short g_z1h[4 * NN * E1],  g_z1l[4 * NN * E1];   // Z1 [NN,E1]
__device__ unsigned short g_t2h[4 * NN * E2],  g_t2l[4 * NN * E2];   // T2^T [E2,NN]
__device__ unsigned short g_z2h[4 * NN * E2],  g_z2l[4 * NN * E2];   // Z2 [NN,E2]
__device__ unsigned short g_t3h[4 * NN * NZ],  g_t3l[4 * NN * NZ];   // T3^T [NZ,NN]
__device__ unsigned short g_z3h[4 * NN * NZ],  g_z3l[4 * NN * NZ];   // Z3 [NN,NZ]
__device__ float g_f1[4 * NN * E1];
__device__ float g_f2[4 * NN * E2];
__device__ float g_f3[4 * NN * NZ];

// ---------------- PTX helpers (sm_100 baseline: cp.async/ldmatrix/mma) ------
__device__ __forceinline__ uint32_t smem_u32(const void* p) {
    uint32_t a;
    asm("{ .reg .u64 t; cvta.to.shared.u64 t, %1; cvt.u32.u64 %0, t; }"
        : "=r"(a) : "l"(p));
    return a;
}
__device__ __forceinline__ void cp16(uint32_t dst, const void* src, int sz) {
    asm volatile("cp.async.cg.shared.global [%0], [%1], 16, %2;"
                 :: "r"(dst), "l"(src), "r"(sz) : "memory");
}
__device__ __forceinline__ void cp_commit() {
    asm volatile("cp.async.commit_group;" ::: "memory");
}
template <int W>
__device__ __forceinline__ void cp_wait() {
    asm volatile("cp.async.wait_group %0;" :: "n"(W) : "memory");
}
__device__ __forceinline__ void ldmat4(uint32_t* r, uint32_t a) {
    asm volatile("ldmatrix.sync.aligned.m8n8.x4.shared.b16 {%0,%1,%2,%3}, [%4];"
                 : "=r"(r[0]), "=r"(r[1]), "=r"(r[2]), "=r"(r[3]) : "r"(a));
}
__device__ __forceinline__ void ldmat2(uint32_t* r, uint32_t a) {
    asm volatile("ldmatrix.sync.aligned.m8n8.x2.shared.b16 {%0,%1}, [%2];"
                 : "=r"(r[0]), "=r"(r[1]) : "r"(a));
}
__device__ __forceinline__ void mma16816(float* d, const uint32_t* a, const uint32_t* b) {
    asm volatile(
        "mma.sync.aligned.m16n8k16.row.col.f32.bf16.bf16.f32 "
        "{%0,%1,%2,%3}, {%4,%5,%6,%7}, {%8,%9}, {%0,%1,%2,%3};"
        : "+f"(d[0]), "+f"(d[1]), "+f"(d[2]), "+f"(d[3])
        : "r"(a[0]), "r"(a[1]), "r"(a[2]), "r"(a[3]), "r"(b[0]), "r"(b[1]));
}

// ---------------- conversion kernels ----------------------------------------
struct Ptrs4 {
    const float* in[4];
    unsigned short* hi[4];
    unsigned short* lo[4];
};

__global__ __launch_bounds__(256) void k_split_nt(Ptrs4 p, int n) {
    const int e = blockIdx.z;
    const float* in = p.in[e];
    __nv_bfloat16* hi = (__nv_bfloat16*)p.hi[e];
    __nv_bfloat16* lo = (__nv_bfloat16*)p.lo[e];
    for (int i = blockIdx.x * 256 + threadIdx.x; i < n; i += gridDim.x * 256) {
        float x = in[i];
        __nv_bfloat16 h = __float2bfloat16(x);
        hi[i] = h;
        lo[i] = __float2bfloat16(x - __bfloat162float(h));
    }
}

__global__ __launch_bounds__(256) void k_split_t(Ptrs4 p, int R, int C) {
    __shared__ float tile[32][33];
    const int e = blockIdx.z;
    const float* in = p.in[e];
    __nv_bfloat16* hi = (__nv_bfloat16*)p.hi[e];
    __nv_bfloat16* lo = (__nv_bfloat16*)p.lo[e];
    const int c0 = blockIdx.x * 32, r0 = blockIdx.y * 32;
    const int tx = threadIdx.x & 31, ty = threadIdx.x >> 5;
#pragma unroll
    for (int i = 0; i < 32; i += 8) {
        int r = r0 + ty + i, c = c0 + tx;
        tile[ty + i][tx] = (r < R && c < C) ? in[(size_t)r * C + c] : 0.0f;
    }
    __syncthreads();
#pragma unroll
    for (int i = 0; i < 32; i += 8) {
        int oc = c0 + ty + i, orr = r0 + tx;
        if (oc < C && orr < R) {
            float x = tile[tx][ty + i];
            __nv_bfloat16 h = __float2bfloat16(x);
            hi[(size_t)oc * R + orr] = h;
            lo[(size_t)oc * R + orr] = __float2bfloat16(x - __bfloat162float(h));
        }
    }
}

// ---------------- mma.sync GEMM ---------------------------------------------
// C_e[M,N] = act(A_e[M,K] @ B_e^T); A [M,K] hi/lo, B [N,K] hi/lo (K-major).
// CTA 128 x BN, 8 warps, K-chunk 16, 2-stage cp.async pipeline.
// ACT: 0 none, 1 tanh, 2 sigmoid.
struct GemmB {
    const unsigned short *Ah[4], *Al[4], *Bh[4], *Bl[4];
    float* C[4];
};

#define KC 16
#define AST 24   // smem row stride in bf16 (48B: 16B-aligned, conflict-free ldmatrix)

template <int BN, int ACT>
__global__ __launch_bounds__(256) void mma_gemm(GemmB p, int M, int N, int K) {
    constexpr int WARP_M = (BN == 128) ? 2 : 4;
    constexpr int MT = (BN == 128) ? 4 : 2;   // m16 tiles per warp
    constexpr int NT = 4;                     // n8 tiles per warp (32 cols)
    constexpr int WTM = MT * 16;
    constexpr int A_ST = 128 * AST;           // bf16 per A stage matrix
    constexpr int B_ST = BN * AST;

    __shared__ __align__(16) unsigned short sA[2][2][A_ST];
    __shared__ __align__(16) unsigned short sB[2][2][B_ST];

    const int tid = threadIdx.x, wid = tid >> 5, lane = tid & 31;
    const int e = blockIdx.z;
    const int row0 = blockIdx.y * 128, col0 = blockIdx.x * BN;
    const int wm = wid % WARP_M, wn = wid / WARP_M;

    const unsigned short* __restrict__ Ah = p.Ah[e];
    const unsigned short* __restrict__ Al = p.Al[e];
    const unsigned short* __restrict__ Bh = p.Bh[e];
    const unsigned short* __restrict__ Bl = p.Bl[e];

    const uint32_t sAb = smem_u32(sA);
    const uint32_t sBb = smem_u32(sB);

    float acc[MT][NT][4];
#pragma unroll
    for (int i = 0; i < MT; i++)
#pragma unroll
        for (int j = 0; j < NT; j++)
#pragma unroll
            for (int q = 0; q < 4; q++) acc[i][j][q] = 0.0f;

    const int lr = tid >> 1, lh = tid & 1;  // load row / 16B-half
    const int nch = (K + KC - 1) / KC;

#define LOAD_STAGE(ST, CC)                                                     \
    do {                                                                       \
        int k0_ = (CC) * KC;                                                   \
        int gk_ = k0_ + lh * 8;                                                \
        {                                                                      \
            int gm_ = row0 + lr;                                               \
            int sz_ = (gm_ < M && gk_ < K) ? 16 : 0;                           \
            size_t go_ = sz_ ? ((size_t)gm_ * K + gk_) : 0;                    \
            uint32_t da_ = sAb + (uint32_t)((((ST) * 2) * A_ST +               \
                                             lr * AST + lh * 8) * 2);          \
            cp16(da_, Ah + go_, sz_);                                          \
            cp16(da_ + A_ST * 2, Al + go_, sz_);                               \
        }                                                                      \
        if (tid < 2 * BN) {                                                    \
            int gn_ = col0 + lr;                                               \
            int sz_ = (gn_ < N && gk_ < K) ? 16 : 0;                           \
            size_t go_ = sz_ ? ((size_t)gn_ * K + gk_) : 0;                    \
            uint32_t db_ = sBb + (uint32_t)((((ST) * 2) * B_ST +               \
                                             lr * AST + lh * 8) * 2);          \
            cp16(db_, Bh + go_, sz_);                                          \
            cp16(db_ + B_ST * 2, Bl + go_, sz_);                               \
        }                                                                      \
    } while (0)

    LOAD_STAGE(0, 0);
    cp_commit();

    const int arow = lane & 15, ak8 = (lane >> 4) * 8;
    const int brow = lane & 7,  bk8 = ((lane >> 3) & 1) * 8;

    int st = 0;
    for (int c = 0; c < nch; c++) {
        if (c + 1 < nch) {
            LOAD_STAGE(st ^ 1, c + 1);
            cp_commit();
            cp_wait<1>();
        } else {
            cp_wait<0>();
        }
        __syncthreads();

        uint32_t afh[MT][4], afl[MT][4];
#pragma unroll
        for (int mt = 0; mt < MT; mt++) {
            uint32_t ad = sAb + (uint32_t)(((st * 2) * A_ST +
                          (wm * WTM + mt * 16 + arow) * AST + ak8) * 2);
            ldmat4(afh[mt], ad);
            ldmat4(afl[mt], ad + A_ST * 2);
        }
        uint32_t bfh[NT][2], bfl[NT][2];
#pragma unroll
        for (int nt = 0; nt < NT; nt++) {
            uint32_t bd = sBb + (uint32_t)(((st * 2) * B_ST +
                          (wn * 32 + nt * 8 + brow) * AST + bk8) * 2);
            ldmat2(bfh[nt], bd);
            ldmat2(bfl[nt], bd + B_ST * 2);
        }
#pragma unroll
        for (int mt = 0; mt < MT; mt++)
#pragma unroll
            for (int nt = 0; nt < NT; nt++) {
                mma16816(acc[mt][nt], afh[mt], bfh[nt]);
                mma16816(acc[mt][nt], afl[mt], bfh[nt]);
                mma16816(acc[mt][nt], afh[mt], bfl[nt]);
            }
        __syncthreads();
        st ^= 1;
    }
#undef LOAD_STAGE

    // Epilogue: d0,d1 -> (row grp, col gc, gc+1); d2,d3 -> (row grp+8, ...)
    float* __restrict__ C = p.C[e];
    const int grp = lane >> 2, gc = (lane & 3) * 2;
#pragma unroll
    for (int mt = 0; mt < MT; mt++)
#pragma unroll
        for (int nt = 0; nt < NT; nt++)
#pragma unroll
            for (int h = 0; h < 2; h++) {
                int m = row0 + wm * WTM + mt * 16 + grp + h * 8;
                int n = col0 + wn * 32 + nt * 8 + gc;
                if (m < M && n < N) {
                    float x0 = acc[mt][nt][h * 2], x1 = acc[mt][nt][h * 2 + 1];
                    if (ACT == 1) { x0 = tanhf(x0); x1 = tanhf(x1); }
                    if (ACT == 2) {
                        x0 = 1.0f / (1.0f + expf(-x0));
                        x1 = 1.0f / (1.0f + expf(-x1));
                    }
                    float2 v = make_float2(x0, x1);
                    *(float2*)(C + (size_t)m * N + n) = v;
                }
            }
}

// ---------------------------------------------------------------------------
extern "C" void kernel_launch(void* const* d_in, const int* in_sizes, int n_in,
                              void* d_out, int out_size) {
    (void)in_sizes; (void)n_in; (void)out_size;

    const float* omics[2] = {(const float*)d_in[0], (const float*)d_in[1]};
    const float* adjs[4] = {(const float*)d_in[2], (const float*)d_in[3],
                            (const float*)d_in[4], (const float*)d_in[5]};
    float* out = (float*)d_out;

#define SYM(v, s) unsigned short* v; cudaGetSymbolAddress((void**)&v, s)
    SYM(xh, g_xh); SYM(xl, g_xl);
    SYM(ajh, g_ajh); SYM(ajl, g_ajl);
    SYM(w1h, g_w1h); SYM(w1l, g_w1l);
    SYM(w2h, g_w2h); SYM(w2l, g_w2l);
    SYM(w3h, g_w3h); SYM(w3l, g_w3l);
    SYM(t1h, g_t1h); SYM(t1l, g_t1l);
    SYM(z1h, g_z1h); SYM(z1l, g_z1l);
    SYM(t2h, g_t2h); SYM(t2l, g_t2l);
    SYM(z2h, g_z2h); SYM(z2l, g_z2l);
    SYM(t3h, g_t3h); SYM(t3l, g_t3l);
    SYM(z3h, g_z3h); SYM(z3l, g_z3l);
#undef SYM
    float *f1, *f2, *f3;
    cudaGetSymbolAddress((void**)&f1, g_f1);
    cudaGetSymbolAddress((void**)&f2, g_f2);
    cudaGetSymbolAddress((void**)&f3, g_f3);

    // ---- input conversions ----
    Ptrs4 pc;
    for (int i = 0; i < 2; i++) {
        pc.in[i] = omics[i];
        pc.hi[i] = xh + (size_t)i * OM;
        pc.lo[i] = xl + (size_t)i * OM;
    }
    k_split_nt<<<dim3(1024, 1, 2), 256>>>(pc, OM);
    for (int i = 0; i < 4; i++) {
        pc.in[i] = adjs[i];
        pc.hi[i] = ajh + (size_t)i * OM;
        pc.lo[i] = ajl + (size_t)i * OM;
    }
    k_split_nt<<<dim3(1024, 1, 4), 256>>>(pc, OM);
    for (int i = 0; i < 4; i++) {
        pc.in[i] = (const float*)d_in[6 + i * 3 + 0];
        pc.hi[i] = w1h + (size_t)i * NN * E1;
        pc.lo[i] = w1l + (size_t)i * NN * E1;
    }
    k_split_t<<<dim3(E1 / 32, (NN + 31) / 32, 4), 256>>>(pc, NN, E1);
    for (int i = 0; i < 4; i++) {
        pc.in[i] = (const float*)d_in[6 + i * 3 + 1];
        pc.hi[i] = w2h + (size_t)i * E1 * E2;
        pc.lo[i] = w2l + (size_t)i * E1 * E2;
    }
    k_split_t<<<dim3(E2 / 32, E1 / 32, 4), 256>>>(pc, E1, E2);
    for (int i = 0; i < 4; i++) {
        pc.in[i] = (const float*)d_in[6 + i * 3 + 2];
        pc.hi[i] = w3h + (size_t)i * E2 * NZ;
        pc.lo[i] = w3l + (size_t)i * E2 * NZ;
    }
    k_split_t<<<dim3(NZ / 32, E2 / 32, 4), 256>>>(pc, E2, NZ);

    const int mb = (NN + 127) / 128;  // 24
    const int xsel[4] = {0, 1, 0, 1};
    GemmB g;

    // L1a: T1 = tanh(X @ W1)   [N=E1, K=NN]
    for (int e = 0; e < 4; e++) {
        g.Ah[e] = xh + (size_t)xsel[e] * OM;  g.Al[e] = xl + (size_t)xsel[e] * OM;
        g.Bh[e] = w1h + (size_t)e * NN * E1;  g.Bl[e] = w1l + (size_t)e * NN * E1;
        g.C[e] = f1 + (size_t)e * NN * E1;
    }
    mma_gemm<128, 1><<<dim3(E1 / 128, mb, 4), 256>>>(g, NN, E1, NN);
    for (int e = 0; e < 4; e++) {
        pc.in[e] = f1 + (size_t)e * NN * E1;
        pc.hi[e] = t1h + (size_t)e * NN * E1;
        pc.lo[e] = t1l + (size_t)e * NN * E1;
    }
    k_split_t<<<dim3(E1 / 32, (NN + 31) / 32, 4), 256>>>(pc, NN, E1);
    // L1b: Z1 = adj @ T1
    for (int e = 0; e < 4; e++) {
        g.Ah[e] = ajh + (size_t)e * OM;       g.Al[e] = ajl + (size_t)e * OM;
        g.Bh[e] = t1h + (size_t)e * NN * E1;  g.Bl[e] = t1l + (size_t)e * NN * E1;
        g.C[e] = f1 + (size_t)e * NN * E1;
    }
    mma_gemm<128, 0><<<dim3(E1 / 128, mb, 4), 256>>>(g, NN, E1, NN);
    for (int e = 0; e < 4; e++) {
        pc.in[e] = f1 + (size_t)e * NN * E1;
        pc.hi[e] = z1h + (size_t)e * NN * E1;
        pc.lo[e] = z1l + (size_t)e * NN * E1;
    }
    k_split_nt<<<dim3(512, 1, 4), 256>>>(pc, NN * E1);
    // L2a: T2 = tanh(Z1 @ W2)  [N=E2, K=E1]
    for (int e = 0; e < 4; e++) {
        g.Ah[e] = z1h + (size_t)e * NN * E1;  g.Al[e] = z1l + (size_t)e * NN * E1;
        g.Bh[e] = w2h + (size_t)e * E1 * E2;  g.Bl[e] = w2l + (size_t)e * E1 * E2;
        g.C[e] = f2 + (size_t)e * NN * E2;
    }
    mma_gemm<128, 1><<<dim3(E2 / 128, mb, 4), 256>>>(g, NN, E2, E1);
    for (int e = 0; e < 4; e++) {
        pc.in[e] = f2 + (size_t)e * NN * E2;
        pc.hi[e] = t2h + (size_t)e * NN * E2;
        pc.lo[e] = t2l + (size_t)e * NN * E2;
    }
    k_split_t<<<dim3(E2 / 32, (NN + 31) / 32, 4), 256>>>(pc, NN, E2);
    // L2b: Z2 = adj @ T2
    for (int e = 0; e < 4; e++) {
        g.Ah[e] = ajh + (size_t)e * OM;       g.Al[e] = ajl + (size_t)e * OM;
        g.Bh[e] = t2h + (size_t)e * NN * E2;  g.Bl[e] = t2l + (size_t)e * NN * E2;
        g.C[e] = f2 + (size_t)e * NN * E2;
    }
    mma_gemm<128, 0><<<dim3(E2 / 128, mb, 4), 256>>>(g, NN, E2, NN);
    for (int e = 0; e < 4; e++) {
        pc.in[e] = f2 + (size_t)e * NN * E2;
        pc.hi[e] = z2h + (size_t)e * NN * E2;
        pc.lo[e] = z2l + (size_t)e * NN * E2;
    }
    k_split_nt<<<dim3(512, 1, 4), 256>>>(pc, NN * E2);
    // L3a: T3 = Z2 @ W3  [N=NZ, K=E2]
    for (int e = 0; e < 4; e++) {
        g.Ah[e] = z2h + (size_t)e * NN * E2;  g.Al[e] = z2l + (size_t)e * NN * E2;
        g.Bh[e] = w3h + (size_t)e * E2 * NZ;  g.Bl[e] = w3l + (size_t)e * E2 * NZ;
        g.C[e] = f3 + (size_t)e * NN * NZ;
    }
    mma_gemm<64, 0><<<dim3(NZ / 64, mb, 4), 256>>>(g, NN, NZ, E2);
    for (int e = 0; e < 4; e++) {
        pc.in[e] = f3 + (size_t)e * NN * NZ;
        pc.hi[e] = t3h + (size_t)e * NN * NZ;
        pc.lo[e] = t3l + (size_t)e * NN * NZ;
    }
    k_split_t<<<dim3(NZ / 32, (NN + 31) / 32, 4), 256>>>(pc, NN, NZ);
    // L3b: Z3 = adj @ T3
    for (int e = 0; e < 4; e++) {
        g.Ah[e] = ajh + (size_t)e * OM;       g.Al[e] = ajl + (size_t)e * OM;
        g.Bh[e] = t3h + (size_t)e * NN * NZ;  g.Bl[e] = t3l + (size_t)e * NN * NZ;
        g.C[e] = f3 + (size_t)e * NN * NZ;
    }
    mma_gemm<64, 0><<<dim3(NZ / 64, mb, 4), 256>>>(g, NN, NZ, NN);
    for (int e = 0; e < 4; e++) {
        pc.in[e] = f3 + (size_t)e * NN * NZ;
        pc.hi[e] = z3h + (size_t)e * NN * NZ;
        pc.lo[e] = z3l + (size_t)e * NN * NZ;
    }
    k_split_nt<<<dim3(512, 1, 4), 256>>>(pc, NN * NZ);
    // Output: out_e = sigmoid(Z3 @ Z3^T)   [M=N=NN, K=NZ]
    GemmB zz;
    for (int e = 0; e < 4; e++) {
        zz.Ah[e] = z3h + (size_t)e * NN * NZ;  zz.Al[e] = z3l + (size_t)e * NN * NZ;
        zz.Bh[e] = z3h + (size_t)e * NN * NZ;  zz.Bl[e] = z3l + (size_t)e * NN * NZ;
        zz.C[e] = out + (size_t)e * OM;
    }
    mma_gemm<128, 2><<<dim3(mb, mb, 4), 256>>>(zz, NN, NN, NZ);
}